// round 14
// baseline (speedup 1.0000x reference)
#include <cuda_runtime.h>
#include <cuda_fp16.h>

// Problem constants
#define B_TOTAL  1024
#define N_IN     1024
#define L_LAYERS 5
#define NPL      2048
#define FANIN    16
#define N_OUT    256
#define WIDTH    (N_IN + (L_LAYERS - 1) * NPL)   // 9216 stored node rows

#define THREADS  128

// Activation tensor, [node][batch] fp16, L2-resident (18.9 MB)
__device__ __align__(16) __half g_vals[(size_t)WIDTH * B_TOTAL];

// 8 batch lanes packed (16 bytes -> one LDG.128 / STG.128)
struct alignas(16) h8 { __half2 a, b, c, d; };

__device__ __forceinline__ float tanh_fast(float x) {
    float y;
    asm("tanh.approx.f32 %0, %1;" : "=f"(y) : "f"(x));
    return y;
}

// fma one source value-vector (8 batch) into a 4x half2 accumulator
#define FMA8(V, WH, ACC)                                   \
    ACC[0] = __hfma2((V).a, (WH), ACC[0]);                 \
    ACC[1] = __hfma2((V).b, (WH), ACC[1]);                 \
    ACC[2] = __hfma2((V).c, (WH), ACC[2]);                 \
    ACC[3] = __hfma2((V).d, (WH), ACC[3]);

// ---------------------------------------------------------------------------
// Tiled transpose: inputs[b][i] (fp32, 1024x1024) -> g_vals[i][b] (fp16)
// ---------------------------------------------------------------------------
__global__ void transpose_kernel(const float* __restrict__ in) {
    __shared__ float tile[32][33];
    const int it = blockIdx.x;
    const int bt = blockIdx.y;
    const int tx = threadIdx.x;   // 0..31
    const int ty = threadIdx.y;   // 0..7

    #pragma unroll
    for (int r = 0; r < 4; ++r) {
        int b = bt * 32 + ty + r * 8;
        int i = it * 32 + tx;
        tile[ty + r * 8][tx] = in[b * N_IN + i];
    }
    __syncthreads();
    #pragma unroll
    for (int r = 0; r < 4; ++r) {
        int i = it * 32 + ty + r * 8;
        int b = bt * 32 + tx;
        g_vals[(size_t)i * B_TOTAL + b] = __float2half(tile[tx][ty + r * 8]);
    }
}

// ---------------------------------------------------------------------------
// One layer. Warp = one node x 256 batch; thread = 8 batch elems (LDG.128).
// Gathers issued in two explicit groups of 8 front-batched loads (MLP=8).
// fp16 HFMA2 accumulation in two 8-term partials, combined in fp32 + bias.
// ---------------------------------------------------------------------------
__global__ __launch_bounds__(THREADS, 8)
void layer_kernel(const int*   __restrict__ src,    // [NPL][FANIN] this layer
                  const float* __restrict__ w,      // [NPL][FANIN]
                  const float* __restrict__ bias,   // [NPL]
                  int node_lo, int write_base,
                  float* __restrict__ out) {
    const int gw   = blockIdx.x * (THREADS / 32) + (threadIdx.x >> 5);
    const int lane = threadIdx.x & 31;
    const int n    = node_lo + (gw >> 2);        // node within layer
    const int b0   = (gw & 3) * 256 + lane * 8;  // first of 8 batch elems

    const int4*   sp = reinterpret_cast<const int4*>(src) + n * (FANIN / 4);
    const float4* wp = reinterpret_cast<const float4*>(w)  + n * (FANIN / 4);
    const __half* vb = g_vals + b0;

    const __half2 z = __float2half2_rn(0.0f);
    __half2 accA[4] = {z, z, z, z};
    __half2 accB[4] = {z, z, z, z};

    // ---- group 0: sources 0..7, 8 loads in flight ----
    {
        const int4 s0 = sp[0], s1 = sp[1];
        h8 v[8];
        v[0] = *reinterpret_cast<const h8*>(vb + (size_t)s0.x * B_TOTAL);
        v[1] = *reinterpret_cast<const h8*>(vb + (size_t)s0.y * B_TOTAL);
        v[2] = *reinterpret_cast<const h8*>(vb + (size_t)s0.z * B_TOTAL);
        v[3] = *reinterpret_cast<const h8*>(vb + (size_t)s0.w * B_TOTAL);
        v[4] = *reinterpret_cast<const h8*>(vb + (size_t)s1.x * B_TOTAL);
        v[5] = *reinterpret_cast<const h8*>(vb + (size_t)s1.y * B_TOTAL);
        v[6] = *reinterpret_cast<const h8*>(vb + (size_t)s1.z * B_TOTAL);
        v[7] = *reinterpret_cast<const h8*>(vb + (size_t)s1.w * B_TOTAL);

        const float4 w0 = wp[0], w1 = wp[1];
        FMA8(v[0], __float2half2_rn(w0.x), accA);
        FMA8(v[1], __float2half2_rn(w0.y), accA);
        FMA8(v[2], __float2half2_rn(w0.z), accA);
        FMA8(v[3], __float2half2_rn(w0.w), accA);
        FMA8(v[4], __float2half2_rn(w1.x), accA);
        FMA8(v[5], __float2half2_rn(w1.y), accA);
        FMA8(v[6], __float2half2_rn(w1.z), accA);
        FMA8(v[7], __float2half2_rn(w1.w), accA);
    }

    // ---- group 1: sources 8..15, 8 loads in flight ----
    {
        const int4 s2 = sp[2], s3 = sp[3];
        h8 v[8];
        v[0] = *reinterpret_cast<const h8*>(vb + (size_t)s2.x * B_TOTAL);
        v[1] = *reinterpret_cast<const h8*>(vb + (size_t)s2.y * B_TOTAL);
        v[2] = *reinterpret_cast<const h8*>(vb + (size_t)s2.z * B_TOTAL);
        v[3] = *reinterpret_cast<const h8*>(vb + (size_t)s2.w * B_TOTAL);
        v[4] = *reinterpret_cast<const h8*>(vb + (size_t)s3.x * B_TOTAL);
        v[5] = *reinterpret_cast<const h8*>(vb + (size_t)s3.y * B_TOTAL);
        v[6] = *reinterpret_cast<const h8*>(vb + (size_t)s3.z * B_TOTAL);
        v[7] = *reinterpret_cast<const h8*>(vb + (size_t)s3.w * B_TOTAL);

        const float4 w2 = wp[2], w3 = wp[3];
        FMA8(v[0], __float2half2_rn(w2.x), accB);
        FMA8(v[1], __float2half2_rn(w2.y), accB);
        FMA8(v[2], __float2half2_rn(w2.z), accB);
        FMA8(v[3], __float2half2_rn(w2.w), accB);
        FMA8(v[4], __float2half2_rn(w3.x), accB);
        FMA8(v[5], __float2half2_rn(w3.y), accB);
        FMA8(v[6], __float2half2_rn(w3.z), accB);
        FMA8(v[7], __float2half2_rn(w3.w), accB);
    }

    const float bi = bias[n];
    float s[8];
    #pragma unroll
    for (int m = 0; m < 4; ++m) {
        float2 pa = __half22float2(accA[m]);
        float2 pb = __half22float2(accB[m]);
        s[2 * m + 0] = pa.x + pb.x + bi;
        s[2 * m + 1] = pa.y + pb.y + bi;
    }

    if (write_base >= 0) {
        h8 r;
        r.a = __floats2half2_rn(tanh_fast(s[0]), tanh_fast(s[1]));
        r.b = __floats2half2_rn(tanh_fast(s[2]), tanh_fast(s[3]));
        r.c = __floats2half2_rn(tanh_fast(s[4]), tanh_fast(s[5]));
        r.d = __floats2half2_rn(tanh_fast(s[6]), tanh_fast(s[7]));
        *reinterpret_cast<h8*>(
            &g_vals[(size_t)(write_base + n) * B_TOTAL + b0]) = r;
    } else {
        const int c = n - node_lo;   // 0..N_OUT-1
        #pragma unroll
        for (int e = 0; e < 8; ++e)
            out[(b0 + e) * N_OUT + c] = 1.0f / (1.0f + __expf(-s[e]));
    }
}

extern "C" void kernel_launch(void* const* d_in, const int* in_sizes, int n_in,
                              void* d_out, int out_size) {
    const float* inputs   = (const float*)d_in[0];
    const int*   edge_src = (const int*)  d_in[1];
    const float* edge_w   = (const float*)d_in[2];
    const float* biases   = (const float*)d_in[3];
    float*       out      = (float*)d_out;

    // 1) inputs -> g_vals[0..N_IN), transposed to [node][batch] fp16
    transpose_kernel<<<dim3(N_IN / 32, B_TOTAL / 32), dim3(32, 8)>>>(inputs);

    // 2) hidden layers 0..3: grid = nodes (block = 4 warps = 1 node x 1024 batch)
    for (int l = 0; l < L_LAYERS - 1; ++l) {
        layer_kernel<<<NPL, THREADS>>>(
            edge_src + (size_t)l * NPL * FANIN,
            edge_w   + (size_t)l * NPL * FANIN,
            biases   + (size_t)l * NPL,
            0, N_IN + l * NPL, out);
    }

    // 3) final layer: last N_OUT nodes, sigmoid, write to out
    {
        const int l = L_LAYERS - 1;
        layer_kernel<<<N_OUT, THREADS>>>(
            edge_src + (size_t)l * NPL * FANIN,
            edge_w   + (size_t)l * NPL * FANIN,
            biases   + (size_t)l * NPL,
            NPL - N_OUT, -1, out);
    }
}